// round 9
// baseline (speedup 1.0000x reference)
#include <cuda_runtime.h>
#include <cuda_fp16.h>

#define NMAX 100000
#define EMAX 1600000
#define GMAX 2048
#define SCAN_BS 512
#define NBLK_MAX ((NMAX + SCAN_BS - 1) / SCAN_BS)

// persistent scratch (no allocs allowed)
__device__ __align__(16) __half g_xwh[NMAX * 64];   // layer-1 features (x@W1), fp16
__device__ __align__(16) __half g_xwh2[NMAX * 64];  // layer-2 features (relu(h1)@W2), fp16
__device__ float g_h[NMAX * 64];      // fp32 aggregation output (layer-2)
__device__ float g_dinv[NMAX];        // rsqrt(degree)
__device__ int   g_cnt[NMAX];         // in-degree counts
__device__ int   g_rowptr[NMAX + 1];  // CSR row pointers (by dst)
__device__ int   g_cur[NMAX];         // fill cursors
__device__ __align__(8) int2 g_csrcw[EMAX];  // CSR packed {src, weight-bits}
__device__ int   g_bsum[NBLK_MAX];    // scan block sums
__device__ int   g_start[GMAX + 1];   // graph row boundaries

__global__ void k_zero_cnt(int N) {
    int i = blockIdx.x * blockDim.x + threadIdx.x;
    if (i < N) g_cnt[i] = 0;
}

// fused: degree count (id < E) + xw1 = x@W1 -> half (id < N*64)
__global__ void k_count_xw1(const int* __restrict__ ei,
                            const float* __restrict__ x,
                            const float* __restrict__ W1, int E, int N) {
    __shared__ float sW[6 * 64];
    for (int t = threadIdx.x; t < 384; t += blockDim.x) sW[t] = W1[t];
    __syncthreads();
    int id = blockIdx.x * blockDim.x + threadIdx.x;
    if (id < E) atomicAdd(&g_cnt[ei[E + id]], 1);
    int row = id >> 6, col = id & 63;
    if (row < N) {
        const float* xr = x + row * 6;
        float s = 0.f;
#pragma unroll
        for (int k = 0; k < 6; k++) s += xr[k] * sW[k * 64 + col];
        g_xwh[id] = __float2half_rn(s);
    }
}

// per-block inclusive scan -> exclusive within block + block totals
__global__ void k_scan1(int N) {
    __shared__ int sh[SCAN_BS];
    int i = blockIdx.x * SCAN_BS + threadIdx.x;
    int v = (i < N) ? g_cnt[i] : 0;
    sh[threadIdx.x] = v;
    __syncthreads();
#pragma unroll
    for (int off = 1; off < SCAN_BS; off <<= 1) {
        int t = (threadIdx.x >= off) ? sh[threadIdx.x - off] : 0;
        __syncthreads();
        sh[threadIdx.x] += t;
        __syncthreads();
    }
    if (i < N) g_rowptr[i] = sh[threadIdx.x] - v;
    if (threadIdx.x == SCAN_BS - 1) g_bsum[blockIdx.x] = sh[threadIdx.x];
}

// block offset (redundant reduce) + rowptr finalize + cursor init + dinv
__global__ void k_scan3(int N, int E) {
    __shared__ int warp_part[SCAN_BS / 32];
    __shared__ int s_off;
    int part = 0;
    for (int j = threadIdx.x; j < blockIdx.x; j += SCAN_BS) part += g_bsum[j];
#pragma unroll
    for (int o = 16; o; o >>= 1) part += __shfl_down_sync(0xffffffffu, part, o);
    if ((threadIdx.x & 31) == 0) warp_part[threadIdx.x >> 5] = part;
    __syncthreads();
    if (threadIdx.x == 0) {
        int t = 0;
#pragma unroll
        for (int w = 0; w < SCAN_BS / 32; w++) t += warp_part[w];
        s_off = t;
    }
    __syncthreads();
    int i = blockIdx.x * SCAN_BS + threadIdx.x;
    if (i < N) {
        int rp = g_rowptr[i] + s_off;
        g_rowptr[i] = rp;
        g_cur[i] = rp;
        g_dinv[i] = rsqrtf((float)(g_cnt[i] + 1));
        if (i == 0) g_rowptr[N] = E;
    }
}

// fused: CSR fill (id < E) + graph bounds from sorted batch (id < N)
__global__ void k_fill_bounds(const int* __restrict__ ei,
                              const int* __restrict__ batch,
                              int E, int N, int G) {
    int id = blockIdx.x * blockDim.x + threadIdx.x;
    if (id < E) {
        int s = ei[id];
        int d = ei[E + id];
        int pos = atomicAdd(&g_cur[d], 1);
        float w = g_dinv[s] * g_dinv[d];
        g_csrcw[pos] = make_int2(s, __float_as_int(w));
    }
    if (id < N) {
        int b = batch[id];
        if (id == 0) {
            for (int g2 = 0; g2 <= b; g2++) g_start[g2] = 0;
        } else {
            int pb = batch[id - 1];
            for (int g2 = pb + 1; g2 <= b; g2++) g_start[g2] = id;
        }
        if (id == N - 1) {
            for (int g2 = b + 1; g2 <= G; g2++) g_start[g2] = N;
        }
    }
}

__device__ __forceinline__ void h8_fma(float* acc, uint4 r, float w) {
    __half2* h = (__half2*)&r;
#pragma unroll
    for (int i = 0; i < 4; i++) {
        float2 f = __half22float2(h[i]);
        acc[2 * i]     += f.x * w;
        acc[2 * i + 1] += f.y * w;
    }
}

// Layer 1 fused: CSR gather over g_xwh + bias/relu + @W2 -> g_xwh2 (fp16)
// 8 threads/node, uint4 per thread (R4-proven gather core).
__global__ void __launch_bounds__(256) k_gather_xw2(const float* __restrict__ b1,
                                                    const float* __restrict__ W2, int N) {
    __shared__ float sW[64 * 64];       // 16KB
    __shared__ float shh[32][65];       // 8 warps * 4 nodes, 64 feats (+1 pad)
    for (int t = threadIdx.x; t < 4096; t += 256) sW[t] = W2[t];
    __syncthreads();
    int id = blockIdx.x * blockDim.x + threadIdx.x;
    int n = id >> 3;
    int c = id & 7;
    int wrow = threadIdx.x >> 3;        // 0..31: warp*4 + group
    float A[8] = {0, 0, 0, 0, 0, 0, 0, 0};
    float B[8] = {0, 0, 0, 0, 0, 0, 0, 0};
    if (n < N) {
        const uint4* __restrict__ xw4 = (const uint4*)g_xwh;
        float di = g_dinv[n];
        h8_fma(A, xw4[n * 8 + c], di * di);
        int k = g_rowptr[n], end = g_rowptr[n + 1];
        for (; k + 1 < end; k += 2) {
            int2 e0 = g_csrcw[k];
            int2 e1 = g_csrcw[k + 1];
            uint4 r0 = xw4[e0.x * 8 + c];
            uint4 r1 = xw4[e1.x * 8 + c];
            h8_fma(A, r0, __int_as_float(e0.y));
            h8_fma(B, r1, __int_as_float(e1.y));
        }
        if (k < end) {
            int2 e0 = g_csrcw[k];
            h8_fma(A, xw4[e0.x * 8 + c], __int_as_float(e0.y));
        }
        // bias + relu, stage to smem
#pragma unroll
        for (int j = 0; j < 8; j++)
            shh[wrow][c * 8 + j] = fmaxf(A[j] + B[j] + b1[c * 8 + j], 0.f);
    }
    __syncwarp();
    if (n < N) {
        // xw2: this thread computes its node's outputs [8c, 8c+8)
        const float* hrow = shh[wrow];
        float o[8] = {0, 0, 0, 0, 0, 0, 0, 0};
#pragma unroll 8
        for (int k = 0; k < 64; k++) {
            float hv = hrow[k];
            const float4* wp = (const float4*)&sW[k * 64 + c * 8];
            float4 wa = wp[0];
            float4 wb = wp[1];
            o[0] += hv * wa.x; o[1] += hv * wa.y; o[2] += hv * wa.z; o[3] += hv * wa.w;
            o[4] += hv * wb.x; o[5] += hv * wb.y; o[6] += hv * wb.z; o[7] += hv * wb.w;
        }
        __half2 p[4];
#pragma unroll
        for (int j = 0; j < 4; j++)
            p[j] = __floats2half2_rn(o[2 * j], o[2 * j + 1]);
        ((uint4*)g_xwh2)[n * 8 + c] = *(uint4*)p;
    }
}

// Layer 2 gather: reads g_xwh2, writes fp32 g_h (R4-proven config)
__global__ void k_gather2(int N) {
    int id = blockIdx.x * blockDim.x + threadIdx.x;
    int n = id >> 3;
    if (n >= N) return;
    int c = id & 7;
    const uint4* __restrict__ xw4 = (const uint4*)g_xwh2;
    float di = g_dinv[n];
    float w0 = di * di;
    float A[8] = {0, 0, 0, 0, 0, 0, 0, 0};
    float B[8] = {0, 0, 0, 0, 0, 0, 0, 0};
    h8_fma(A, xw4[n * 8 + c], w0);
    int k = g_rowptr[n], end = g_rowptr[n + 1];
    for (; k + 1 < end; k += 2) {
        int2 e0 = g_csrcw[k];
        int2 e1 = g_csrcw[k + 1];
        uint4 r0 = xw4[e0.x * 8 + c];
        uint4 r1 = xw4[e1.x * 8 + c];
        h8_fma(A, r0, __int_as_float(e0.y));
        h8_fma(B, r1, __int_as_float(e1.y));
    }
    if (k < end) {
        int2 e0 = g_csrcw[k];
        h8_fma(A, xw4[e0.x * 8 + c], __int_as_float(e0.y));
    }
    float4* out4 = (float4*)(g_h + n * 64 + c * 8);
    out4[0] = make_float4(A[0] + B[0], A[1] + B[1], A[2] + B[2], A[3] + B[3]);
    out4[1] = make_float4(A[4] + B[4], A[5] + B[5], A[6] + B[6], A[7] + B[7]);
}

// fused: relu(h2+b2) mean-pool + concat embeddings + lin1 + relu + lin2
__global__ void k_final(const float* __restrict__ b2,
                        const int* __restrict__ lig, const int* __restrict__ addv,
                        const int* __restrict__ bas, const int* __restrict__ ary,
                        const float* __restrict__ e_l, const float* __restrict__ e_a,
                        const float* __restrict__ e_b, const float* __restrict__ e_r,
                        const float* __restrict__ l1W, const float* __restrict__ l1b,
                        const float* __restrict__ l2W, const float* __restrict__ l2b,
                        float* __restrict__ out, int G) {
    __shared__ float cat[8][128];
    int lane = threadIdx.x & 31;
    int w = threadIdx.x >> 5;
    int g = blockIdx.x * 8 + w;
    if (g >= G) return;
    int s = g_start[g], e = g_start[g + 1];
    float bias0 = b2[lane], bias1 = b2[lane + 32];
    float a0 = 0.f, a1 = 0.f;
    for (int r = s; r < e; r++) {
        a0 += fmaxf(g_h[r * 64 + lane] + bias0, 0.f);
        a1 += fmaxf(g_h[r * 64 + 32 + lane] + bias1, 0.f);
    }
    float inv = 1.0f / fmaxf((float)(e - s), 1.0f);
    cat[w][lane] = a0 * inv;
    cat[w][lane + 32] = a1 * inv;
    if (lane < 16) {
        cat[w][64 + lane]  = e_l[lig[g] * 16 + lane];
        cat[w][80 + lane]  = e_a[addv[g] * 16 + lane];
        cat[w][96 + lane]  = e_b[bas[g] * 16 + lane];
        cat[w][112 + lane] = e_r[ary[g] * 16 + lane];
    }
    __syncwarp();
    float h0 = l1b[lane], h1 = l1b[lane + 32];
#pragma unroll 8
    for (int k = 0; k < 128; k++) {
        float v = cat[w][k];
        h0 += v * l1W[k * 64 + lane];
        h1 += v * l1W[k * 64 + lane + 32];
    }
    h0 = fmaxf(h0, 0.f);
    h1 = fmaxf(h1, 0.f);
    float p = h0 * l2W[lane] + h1 * l2W[lane + 32];
#pragma unroll
    for (int off = 16; off > 0; off >>= 1) p += __shfl_down_sync(0xffffffffu, p, off);
    if (lane == 0) out[g] = p + l2b[0];
}

extern "C" void kernel_launch(void* const* d_in, const int* in_sizes, int n_in,
                              void* d_out, int out_size) {
    const float* x      = (const float*)d_in[0];
    const int*   ei     = (const int*)d_in[1];
    const int*   batch  = (const int*)d_in[2];
    const int*   lig    = (const int*)d_in[3];
    const int*   addv   = (const int*)d_in[4];
    const int*   bas    = (const int*)d_in[5];
    const int*   ary    = (const int*)d_in[6];
    const float* e_l    = (const float*)d_in[7];
    const float* e_a    = (const float*)d_in[8];
    const float* e_b    = (const float*)d_in[9];
    const float* e_r    = (const float*)d_in[10];
    const float* W1     = (const float*)d_in[11];
    const float* b1     = (const float*)d_in[12];
    const float* W2     = (const float*)d_in[13];
    const float* b2     = (const float*)d_in[14];
    const float* l1W    = (const float*)d_in[15];
    const float* l1b    = (const float*)d_in[16];
    const float* l2W    = (const float*)d_in[17];
    const float* l2b    = (const float*)d_in[18];
    float* out = (float*)d_out;

    int N = in_sizes[0] / 6;
    int E = in_sizes[1] / 2;
    int G = out_size;
    const int T = 256;
    int nb = (N + SCAN_BS - 1) / SCAN_BS;
    long long cw = (long long)N * 64 > E ? (long long)N * 64 : E;
    long long fb = E > N ? E : N;

    // build dst-CSR + dinv (xw1 and bounds ride along)
    k_zero_cnt<<<(N + T - 1) / T, T>>>(N);
    k_count_xw1<<<(int)((cw + T - 1) / T), T>>>(ei, x, W1, E, N);
    k_scan1<<<nb, SCAN_BS>>>(N);
    k_scan3<<<nb, SCAN_BS>>>(N, E);
    k_fill_bounds<<<(int)((fb + T - 1) / T), T>>>(ei, batch, E, N, G);

    // layer 1 gather + bias/relu + @W2 (fused)
    k_gather_xw2<<<(N * 8 + T - 1) / T, T>>>(b1, W2, N);

    // layer 2 gather
    k_gather2<<<(N * 8 + T - 1) / T, T>>>(N);

    // readout
    k_final<<<(G + 7) / 8, 256>>>(b2, lig, addv, bas, ary, e_l, e_a, e_b, e_r,
                                  l1W, l1b, l2W, l2b, out, G);
}

// round 11
// speedup vs baseline: 1.1707x; 1.1707x over previous
#include <cuda_runtime.h>
#include <cuda_fp16.h>

#define NMAX 100000
#define EMAX 1600000
#define GMAX 2048
#define SCAN_BS 512
#define NBLK_MAX ((NMAX + SCAN_BS - 1) / SCAN_BS)

// persistent scratch (no allocs allowed)
__device__ __align__(16) __half g_xwh[NMAX * 64];  // fp16 feature buffer (matmul outputs)
__device__ float g_h[NMAX * 64];      // fp32 aggregation output
__device__ float g_dinv[NMAX];        // rsqrt(degree)
__device__ int   g_cnt[NMAX];         // in-degree counts
__device__ int   g_rowptr[NMAX + 1];  // CSR row pointers (by dst)
__device__ int   g_cur[NMAX];         // fill cursors
__device__ __align__(8) int2 g_csrcw[EMAX];  // CSR packed {src, weight-bits}
__device__ int   g_bsum[NBLK_MAX];    // scan block sums
__device__ int   g_start[GMAX + 1];   // graph row boundaries

__global__ void k_zero_cnt(int N) {
    int i = blockIdx.x * blockDim.x + threadIdx.x;
    if (i < N) g_cnt[i] = 0;
}

// fused: degree count (id < E) + xw1 = x@W1 -> half (id < N*64)
__global__ void k_count_xw1(const int* __restrict__ ei,
                            const float* __restrict__ x,
                            const float* __restrict__ W1, int E, int N) {
    __shared__ float sW[6 * 64];
    for (int t = threadIdx.x; t < 384; t += blockDim.x) sW[t] = W1[t];
    __syncthreads();
    int id = blockIdx.x * blockDim.x + threadIdx.x;
    if (id < E) atomicAdd(&g_cnt[ei[E + id]], 1);
    int row = id >> 6, col = id & 63;
    if (row < N) {
        const float* xr = x + row * 6;
        float s = 0.f;
#pragma unroll
        for (int k = 0; k < 6; k++) s += xr[k] * sW[k * 64 + col];
        g_xwh[id] = __float2half_rn(s);
    }
}

// per-block scan (warp shuffles) -> exclusive within block + block totals
__global__ void k_scan1(int N) {
    __shared__ int wsum[SCAN_BS / 32];
    int i = blockIdx.x * SCAN_BS + threadIdx.x;
    int v = (i < N) ? g_cnt[i] : 0;
    int lane = threadIdx.x & 31, wid = threadIdx.x >> 5;
    int inc = v;
#pragma unroll
    for (int o = 1; o < 32; o <<= 1) {
        int t = __shfl_up_sync(0xffffffffu, inc, o);
        if (lane >= o) inc += t;
    }
    if (lane == 31) wsum[wid] = inc;
    __syncthreads();
    if (wid == 0) {
        int t = (lane < SCAN_BS / 32) ? wsum[lane] : 0;
#pragma unroll
        for (int o = 1; o < SCAN_BS / 32; o <<= 1) {
            int u = __shfl_up_sync(0xffffffffu, t, o);
            if (lane >= o) t += u;
        }
        if (lane < SCAN_BS / 32) wsum[lane] = t;
    }
    __syncthreads();
    int base = (wid > 0) ? wsum[wid - 1] : 0;
    if (i < N) g_rowptr[i] = base + inc - v;
    if (threadIdx.x == SCAN_BS - 1) g_bsum[blockIdx.x] = wsum[SCAN_BS / 32 - 1];
}

// block offset (redundant reduce) + rowptr finalize + cursor init + dinv
__global__ void k_scan3(int N, int E) {
    __shared__ int warp_part[SCAN_BS / 32];
    __shared__ int s_off;
    int part = 0;
    for (int j = threadIdx.x; j < blockIdx.x; j += SCAN_BS) part += g_bsum[j];
#pragma unroll
    for (int o = 16; o; o >>= 1) part += __shfl_down_sync(0xffffffffu, part, o);
    if ((threadIdx.x & 31) == 0) warp_part[threadIdx.x >> 5] = part;
    __syncthreads();
    if (threadIdx.x == 0) {
        int t = 0;
#pragma unroll
        for (int w = 0; w < SCAN_BS / 32; w++) t += warp_part[w];
        s_off = t;
    }
    __syncthreads();
    int i = blockIdx.x * SCAN_BS + threadIdx.x;
    if (i < N) {
        int rp = g_rowptr[i] + s_off;
        g_rowptr[i] = rp;
        g_cur[i] = rp;
        g_dinv[i] = rsqrtf((float)(g_cnt[i] + 1));
        if (i == 0) g_rowptr[N] = E;
    }
}

// fused: CSR fill (id < E) + graph bounds from sorted batch (id < N)
__global__ void k_fill_bounds(const int* __restrict__ ei,
                              const int* __restrict__ batch,
                              int E, int N, int G) {
    int id = blockIdx.x * blockDim.x + threadIdx.x;
    if (id < E) {
        int s = ei[id];
        int d = ei[E + id];
        int pos = atomicAdd(&g_cur[d], 1);
        float w = g_dinv[s] * g_dinv[d];
        g_csrcw[pos] = make_int2(s, __float_as_int(w));
    }
    if (id < N) {
        int b = batch[id];
        if (id == 0) {
            for (int g2 = 0; g2 <= b; g2++) g_start[g2] = 0;
        } else {
            int pb = batch[id - 1];
            for (int g2 = pb + 1; g2 <= b; g2++) g_start[g2] = id;
        }
        if (id == N - 1) {
            for (int g2 = b + 1; g2 <= G; g2++) g_start[g2] = N;
        }
    }
}

__device__ __forceinline__ void h8_fma(float* acc, uint4 r, float w) {
    __half2* h = (__half2*)&r;
#pragma unroll
    for (int i = 0; i < 4; i++) {
        float2 f = __half22float2(h[i]);
        acc[2 * i]     += f.x * w;
        acc[2 * i + 1] += f.y * w;
    }
}

// CSR gather, warp-per-node: lane = j*8 + c; group j walks edges k0+j stride 4.
// Each thread owns feature chunk c (uint4 = 8 halves). Cross-group reduce at end.
__global__ void __launch_bounds__(256) k_gather(int N) {
    int id = blockIdx.x * blockDim.x + threadIdx.x;
    int n = id >> 5;
    if (n >= N) return;
    int lane = threadIdx.x & 31;
    int c = lane & 7;
    int j = lane >> 3;
    const uint4* __restrict__ xw4 = (const uint4*)g_xwh;  // row = 8 uint4
    float A[8] = {0, 0, 0, 0, 0, 0, 0, 0};
    float B[8] = {0, 0, 0, 0, 0, 0, 0, 0};
    float di = g_dinv[n];
    if (j == 0) h8_fma(A, xw4[n * 8 + c], di * di);
    int k = g_rowptr[n] + j, end = g_rowptr[n + 1];
    for (; k + 4 < end; k += 8) {
        int2 e0 = g_csrcw[k];
        int2 e1 = g_csrcw[k + 4];
        uint4 r0 = xw4[e0.x * 8 + c];
        uint4 r1 = xw4[e1.x * 8 + c];
        h8_fma(A, r0, __int_as_float(e0.y));
        h8_fma(B, r1, __int_as_float(e1.y));
    }
    if (k < end) {
        int2 e0 = g_csrcw[k];
        h8_fma(A, xw4[e0.x * 8 + c], __int_as_float(e0.y));
    }
    // combine B into A, then reduce across the 4 groups (lanes +16, +8)
#pragma unroll
    for (int q = 0; q < 8; q++) {
        float a = A[q] + B[q];
        a += __shfl_down_sync(0xffffffffu, a, 16);
        a += __shfl_down_sync(0xffffffffu, a, 8);
        A[q] = a;
    }
    if (j == 0) {
        float4* out4 = (float4*)(g_h + n * 64 + c * 8);
        out4[0] = make_float4(A[0], A[1], A[2], A[3]);
        out4[1] = make_float4(A[4], A[5], A[6], A[7]);
    }
}

// g_xwh = half(relu(g_h + b1) @ W2)   (4 rows per warp, register-blocked)
__global__ void k_xw2(const float* __restrict__ b1, const float* __restrict__ W, int N) {
    __shared__ float sW[64 * 64];
    for (int t = threadIdx.x; t < 4096; t += blockDim.x) sW[t] = W[t];
    __syncthreads();
    int wrp = (blockIdx.x * blockDim.x + threadIdx.x) >> 5;
    int lane = threadIdx.x & 31;
    int r0 = wrp * 4;
    if (r0 >= N) return;
    float bl = b1[lane], bh = b1[lane + 32];
    float alo[4], ahi[4];
#pragma unroll
    for (int r = 0; r < 4; r++) {
        int row = r0 + r;
        if (row < N) {
            alo[r] = fmaxf(g_h[row * 64 + lane] + bl, 0.f);
            ahi[r] = fmaxf(g_h[row * 64 + 32 + lane] + bh, 0.f);
        } else { alo[r] = 0.f; ahi[r] = 0.f; }
    }
    float s0[4] = {0.f, 0.f, 0.f, 0.f};
    float s1[4] = {0.f, 0.f, 0.f, 0.f};
#pragma unroll
    for (int k = 0; k < 32; k++) {
        float w0 = sW[k * 64 + lane];
        float w1 = sW[k * 64 + lane + 32];
#pragma unroll
        for (int r = 0; r < 4; r++) {
            float vv = __shfl_sync(0xffffffffu, alo[r], k);
            s0[r] += vv * w0;
            s1[r] += vv * w1;
        }
    }
#pragma unroll
    for (int k = 0; k < 32; k++) {
        float w0 = sW[(k + 32) * 64 + lane];
        float w1 = sW[(k + 32) * 64 + lane + 32];
#pragma unroll
        for (int r = 0; r < 4; r++) {
            float vv = __shfl_sync(0xffffffffu, ahi[r], k);
            s0[r] += vv * w0;
            s1[r] += vv * w1;
        }
    }
#pragma unroll
    for (int r = 0; r < 4; r++) {
        int row = r0 + r;
        if (row < N) {
            g_xwh[row * 64 + lane]      = __float2half_rn(s0[r]);
            g_xwh[row * 64 + lane + 32] = __float2half_rn(s1[r]);
        }
    }
}

// fused: relu(h2+b2) mean-pool + concat embeddings + lin1 + relu + lin2
__global__ void k_final(const float* __restrict__ b2,
                        const int* __restrict__ lig, const int* __restrict__ addv,
                        const int* __restrict__ bas, const int* __restrict__ ary,
                        const float* __restrict__ e_l, const float* __restrict__ e_a,
                        const float* __restrict__ e_b, const float* __restrict__ e_r,
                        const float* __restrict__ l1W, const float* __restrict__ l1b,
                        const float* __restrict__ l2W, const float* __restrict__ l2b,
                        float* __restrict__ out, int G) {
    __shared__ float cat[8][128];
    int lane = threadIdx.x & 31;
    int w = threadIdx.x >> 5;
    int g = blockIdx.x * 8 + w;
    if (g >= G) return;
    int s = g_start[g], e = g_start[g + 1];
    float bias0 = b2[lane], bias1 = b2[lane + 32];
    float a0 = 0.f, a1 = 0.f;
    for (int r = s; r < e; r++) {
        a0 += fmaxf(g_h[r * 64 + lane] + bias0, 0.f);
        a1 += fmaxf(g_h[r * 64 + 32 + lane] + bias1, 0.f);
    }
    float inv = 1.0f / fmaxf((float)(e - s), 1.0f);
    cat[w][lane] = a0 * inv;
    cat[w][lane + 32] = a1 * inv;
    if (lane < 16) {
        cat[w][64 + lane]  = e_l[lig[g] * 16 + lane];
        cat[w][80 + lane]  = e_a[addv[g] * 16 + lane];
        cat[w][96 + lane]  = e_b[bas[g] * 16 + lane];
        cat[w][112 + lane] = e_r[ary[g] * 16 + lane];
    }
    __syncwarp();
    float h0 = l1b[lane], h1 = l1b[lane + 32];
#pragma unroll 8
    for (int k = 0; k < 128; k++) {
        float v = cat[w][k];
        h0 += v * l1W[k * 64 + lane];
        h1 += v * l1W[k * 64 + lane + 32];
    }
    h0 = fmaxf(h0, 0.f);
    h1 = fmaxf(h1, 0.f);
    float p = h0 * l2W[lane] + h1 * l2W[lane + 32];
#pragma unroll
    for (int off = 16; off > 0; off >>= 1) p += __shfl_down_sync(0xffffffffu, p, off);
    if (lane == 0) out[g] = p + l2b[0];
}

extern "C" void kernel_launch(void* const* d_in, const int* in_sizes, int n_in,
                              void* d_out, int out_size) {
    const float* x      = (const float*)d_in[0];
    const int*   ei     = (const int*)d_in[1];
    const int*   batch  = (const int*)d_in[2];
    const int*   lig    = (const int*)d_in[3];
    const int*   addv   = (const int*)d_in[4];
    const int*   bas    = (const int*)d_in[5];
    const int*   ary    = (const int*)d_in[6];
    const float* e_l    = (const float*)d_in[7];
    const float* e_a    = (const float*)d_in[8];
    const float* e_b    = (const float*)d_in[9];
    const float* e_r    = (const float*)d_in[10];
    const float* W1     = (const float*)d_in[11];
    const float* b1     = (const float*)d_in[12];
    const float* W2     = (const float*)d_in[13];
    const float* b2     = (const float*)d_in[14];
    const float* l1W    = (const float*)d_in[15];
    const float* l1b    = (const float*)d_in[16];
    const float* l2W    = (const float*)d_in[17];
    const float* l2b    = (const float*)d_in[18];
    float* out = (float*)d_out;

    int N = in_sizes[0] / 6;
    int E = in_sizes[1] / 2;
    int G = out_size;
    const int T = 256;
    int nb = (N + SCAN_BS - 1) / SCAN_BS;
    long long cw = (long long)N * 64 > E ? (long long)N * 64 : E;
    long long fb = E > N ? E : N;

    // build dst-CSR + dinv (xw1 and bounds ride along)
    k_zero_cnt<<<(N + T - 1) / T, T>>>(N);
    k_count_xw1<<<(int)((cw + T - 1) / T), T>>>(ei, x, W1, E, N);
    k_scan1<<<nb, SCAN_BS>>>(N);
    k_scan3<<<nb, SCAN_BS>>>(N, E);
    k_fill_bounds<<<(int)((fb + T - 1) / T), T>>>(ei, batch, E, N, G);

    // layer 1 (warp per node)
    k_gather<<<(N * 32 + T - 1) / T, T>>>(N);

    // layer 2
    k_xw2<<<((N + 3) / 4 * 32 + T - 1) / T, T>>>(b1, W2, N);
    k_gather<<<(N * 32 + T - 1) / T, T>>>(N);

    // readout
    k_final<<<(G + 7) / 8, 256>>>(b2, lig, addv, bas, ary, e_l, e_a, e_b, e_r,
                                  l1W, l1b, l2W, l2b, out, G);
}

// round 14
// speedup vs baseline: 1.2502x; 1.0679x over previous
#include <cuda_runtime.h>
#include <cuda_fp16.h>

#define NMAX 100000
#define EMAX 1600000
#define GMAX 2048
#define SCAN_BS 512
#define NBLK_MAX ((NMAX + SCAN_BS - 1) / SCAN_BS)

// persistent scratch (no allocs allowed)
__device__ __align__(16) __half g_xwh[NMAX * 64];  // fp16 feature buffer (matmul outputs)
__device__ float g_h[NMAX * 64];      // fp32 aggregation output
__device__ float g_dinv[NMAX];        // rsqrt(degree)
__device__ int   g_cnt[NMAX];         // in-degree counts
__device__ int   g_rowptr[NMAX + 1];  // CSR row pointers (by dst)
__device__ int   g_rank[EMAX];        // per-edge rank within its dst row
__device__ __align__(8) int2 g_csrcw[EMAX];  // CSR packed {src, weight-bits}
__device__ int   g_bsum[NBLK_MAX];    // scan block sums
__device__ int   g_start[GMAX + 1];   // graph row boundaries

__global__ void k_zero_cnt(int N) {
    int i = blockIdx.x * blockDim.x + threadIdx.x;
    if (i < N) g_cnt[i] = 0;
}

// fused: degree count -> rank capture (id < E) + xw1 = x@W1 -> half (id < N*64)
// The atomic's return latency is hidden by the co-resident xw1 FFMA warps.
__global__ void k_count_xw1(const int* __restrict__ ei,
                            const float* __restrict__ x,
                            const float* __restrict__ W1, int E, int N) {
    __shared__ float sW[6 * 64];
    for (int t = threadIdx.x; t < 384; t += blockDim.x) sW[t] = W1[t];
    __syncthreads();
    int id = blockIdx.x * blockDim.x + threadIdx.x;
    if (id < E) {
        int pos = atomicAdd(&g_cnt[ei[E + id]], 1);
        g_rank[id] = pos;
    }
    int row = id >> 6, col = id & 63;
    if (row < N) {
        const float* xr = x + row * 6;
        float s = 0.f;
#pragma unroll
        for (int k = 0; k < 6; k++) s += xr[k] * sW[k * 64 + col];
        g_xwh[id] = __float2half_rn(s);
    }
}

// per-block inclusive scan -> exclusive within block + block totals
__global__ void k_scan1(int N) {
    __shared__ int sh[SCAN_BS];
    int i = blockIdx.x * SCAN_BS + threadIdx.x;
    int v = (i < N) ? g_cnt[i] : 0;
    sh[threadIdx.x] = v;
    __syncthreads();
#pragma unroll
    for (int off = 1; off < SCAN_BS; off <<= 1) {
        int t = (threadIdx.x >= off) ? sh[threadIdx.x - off] : 0;
        __syncthreads();
        sh[threadIdx.x] += t;
        __syncthreads();
    }
    if (i < N) g_rowptr[i] = sh[threadIdx.x] - v;
    if (threadIdx.x == SCAN_BS - 1) g_bsum[blockIdx.x] = sh[threadIdx.x];
}

// block offset (redundant reduce) + rowptr finalize + dinv
__global__ void k_scan3(int N, int E) {
    __shared__ int warp_part[SCAN_BS / 32];
    __shared__ int s_off;
    int part = 0;
    for (int j = threadIdx.x; j < blockIdx.x; j += SCAN_BS) part += g_bsum[j];
#pragma unroll
    for (int o = 16; o; o >>= 1) part += __shfl_down_sync(0xffffffffu, part, o);
    if ((threadIdx.x & 31) == 0) warp_part[threadIdx.x >> 5] = part;
    __syncthreads();
    if (threadIdx.x == 0) {
        int t = 0;
#pragma unroll
        for (int w = 0; w < SCAN_BS / 32; w++) t += warp_part[w];
        s_off = t;
    }
    __syncthreads();
    int i = blockIdx.x * SCAN_BS + threadIdx.x;
    if (i < N) {
        g_rowptr[i] += s_off;
        g_dinv[i] = rsqrtf((float)(g_cnt[i] + 1));
        if (i == 0) g_rowptr[N] = E;
    }
}

// fused: CSR fill WITHOUT atomics (pos = rowptr[d] + rank[e]) + graph bounds
__global__ void k_fill_bounds(const int* __restrict__ ei,
                              const int* __restrict__ batch,
                              int E, int N, int G) {
    int id = blockIdx.x * blockDim.x + threadIdx.x;
    if (id < E) {
        int s = ei[id];
        int d = ei[E + id];
        int pos = g_rowptr[d] + g_rank[id];
        float w = g_dinv[s] * g_dinv[d];
        g_csrcw[pos] = make_int2(s, __float_as_int(w));
    }
    if (id < N) {
        int b = batch[id];
        if (id == 0) {
            for (int g2 = 0; g2 <= b; g2++) g_start[g2] = 0;
        } else {
            int pb = batch[id - 1];
            for (int g2 = pb + 1; g2 <= b; g2++) g_start[g2] = id;
        }
        if (id == N - 1) {
            for (int g2 = b + 1; g2 <= G; g2++) g_start[g2] = N;
        }
    }
}

__device__ __forceinline__ void h8_fma(float* acc, uint4 r, float w) {
    __half2* h = (__half2*)&r;
#pragma unroll
    for (int i = 0; i < 4; i++) {
        float2 f = __half22float2(h[i]);
        acc[2 * i]     += f.x * w;
        acc[2 * i + 1] += f.y * w;
    }
}

// CSR gather: g_h[n,:] = dinv^2 * xw[n,:] + sum_e w_e * xw[src_e,:]
// 8 threads/node, one uint4 (8 halves) each; 2-way unroll (R4 proven config)
__global__ void k_gather(int N) {
    int id = blockIdx.x * blockDim.x + threadIdx.x;
    int n = id >> 3;
    if (n >= N) return;
    int c = id & 7;
    const uint4* __restrict__ xw4 = (const uint4*)g_xwh;  // row = 8 uint4
    float di = g_dinv[n];
    float w0 = di * di;
    float A[8] = {0, 0, 0, 0, 0, 0, 0, 0};
    float B[8] = {0, 0, 0, 0, 0, 0, 0, 0};
    h8_fma(A, xw4[n * 8 + c], w0);
    int k = g_rowptr[n], end = g_rowptr[n + 1];
    for (; k + 1 < end; k += 2) {
        int2 e0 = g_csrcw[k];
        int2 e1 = g_csrcw[k + 1];
        uint4 r0 = xw4[e0.x * 8 + c];
        uint4 r1 = xw4[e1.x * 8 + c];
        h8_fma(A, r0, __int_as_float(e0.y));
        h8_fma(B, r1, __int_as_float(e1.y));
    }
    if (k < end) {
        int2 e0 = g_csrcw[k];
        h8_fma(A, xw4[e0.x * 8 + c], __int_as_float(e0.y));
    }
    float4* out4 = (float4*)(g_h + n * 64 + c * 8);
    out4[0] = make_float4(A[0] + B[0], A[1] + B[1], A[2] + B[2], A[3] + B[3]);
    out4[1] = make_float4(A[4] + B[4], A[5] + B[5], A[6] + B[6], A[7] + B[7]);
}

// g_xwh = half(relu(g_h + b1) @ W2)   (4 rows per warp, register-blocked)
__global__ void k_xw2(const float* __restrict__ b1, const float* __restrict__ W, int N) {
    __shared__ float sW[64 * 64];
    for (int t = threadIdx.x; t < 4096; t += blockDim.x) sW[t] = W[t];
    __syncthreads();
    int wrp = (blockIdx.x * blockDim.x + threadIdx.x) >> 5;
    int lane = threadIdx.x & 31;
    int r0 = wrp * 4;
    if (r0 >= N) return;
    float bl = b1[lane], bh = b1[lane + 32];
    float alo[4], ahi[4];
#pragma unroll
    for (int r = 0; r < 4; r++) {
        int row = r0 + r;
        if (row < N) {
            alo[r] = fmaxf(g_h[row * 64 + lane] + bl, 0.f);
            ahi[r] = fmaxf(g_h[row * 64 + 32 + lane] + bh, 0.f);
        } else { alo[r] = 0.f; ahi[r] = 0.f; }
    }
    float s0[4] = {0.f, 0.f, 0.f, 0.f};
    float s1[4] = {0.f, 0.f, 0.f, 0.f};
#pragma unroll
    for (int k = 0; k < 32; k++) {
        float w0 = sW[k * 64 + lane];
        float w1 = sW[k * 64 + lane + 32];
#pragma unroll
        for (int r = 0; r < 4; r++) {
            float vv = __shfl_sync(0xffffffffu, alo[r], k);
            s0[r] += vv * w0;
            s1[r] += vv * w1;
        }
    }
#pragma unroll
    for (int k = 0; k < 32; k++) {
        float w0 = sW[(k + 32) * 64 + lane];
        float w1 = sW[(k + 32) * 64 + lane + 32];
#pragma unroll
        for (int r = 0; r < 4; r++) {
            float vv = __shfl_sync(0xffffffffu, ahi[r], k);
            s0[r] += vv * w0;
            s1[r] += vv * w1;
        }
    }
#pragma unroll
    for (int r = 0; r < 4; r++) {
        int row = r0 + r;
        if (row < N) {
            g_xwh[row * 64 + lane]      = __float2half_rn(s0[r]);
            g_xwh[row * 64 + lane + 32] = __float2half_rn(s1[r]);
        }
    }
}

// fused: relu(h2+b2) mean-pool + concat embeddings + lin1 + relu + lin2
__global__ void k_final(const float* __restrict__ b2,
                        const int* __restrict__ lig, const int* __restrict__ addv,
                        const int* __restrict__ bas, const int* __restrict__ ary,
                        const float* __restrict__ e_l, const float* __restrict__ e_a,
                        const float* __restrict__ e_b, const float* __restrict__ e_r,
                        const float* __restrict__ l1W, const float* __restrict__ l1b,
                        const float* __restrict__ l2W, const float* __restrict__ l2b,
                        float* __restrict__ out, int G) {
    __shared__ float cat[8][128];
    int lane = threadIdx.x & 31;
    int w = threadIdx.x >> 5;
    int g = blockIdx.x * 8 + w;
    if (g >= G) return;
    int s = g_start[g], e = g_start[g + 1];
    float bias0 = b2[lane], bias1 = b2[lane + 32];
    float a0 = 0.f, a1 = 0.f;
    for (int r = s; r < e; r++) {
        a0 += fmaxf(g_h[r * 64 + lane] + bias0, 0.f);
        a1 += fmaxf(g_h[r * 64 + 32 + lane] + bias1, 0.f);
    }
    float inv = 1.0f / fmaxf((float)(e - s), 1.0f);
    cat[w][lane] = a0 * inv;
    cat[w][lane + 32] = a1 * inv;
    if (lane < 16) {
        cat[w][64 + lane]  = e_l[lig[g] * 16 + lane];
        cat[w][80 + lane]  = e_a[addv[g] * 16 + lane];
        cat[w][96 + lane]  = e_b[bas[g] * 16 + lane];
        cat[w][112 + lane] = e_r[ary[g] * 16 + lane];
    }
    __syncwarp();
    float h0 = l1b[lane], h1 = l1b[lane + 32];
#pragma unroll 8
    for (int k = 0; k < 128; k++) {
        float v = cat[w][k];
        h0 += v * l1W[k * 64 + lane];
        h1 += v * l1W[k * 64 + lane + 32];
    }
    h0 = fmaxf(h0, 0.f);
    h1 = fmaxf(h1, 0.f);
    float p = h0 * l2W[lane] + h1 * l2W[lane + 32];
#pragma unroll
    for (int off = 16; off > 0; off >>= 1) p += __shfl_down_sync(0xffffffffu, p, off);
    if (lane == 0) out[g] = p + l2b[0];
}

extern "C" void kernel_launch(void* const* d_in, const int* in_sizes, int n_in,
                              void* d_out, int out_size) {
    const float* x      = (const float*)d_in[0];
    const int*   ei     = (const int*)d_in[1];
    const int*   batch  = (const int*)d_in[2];
    const int*   lig    = (const int*)d_in[3];
    const int*   addv   = (const int*)d_in[4];
    const int*   bas    = (const int*)d_in[5];
    const int*   ary    = (const int*)d_in[6];
    const float* e_l    = (const float*)d_in[7];
    const float* e_a    = (const float*)d_in[8];
    const float* e_b    = (const float*)d_in[9];
    const float* e_r    = (const float*)d_in[10];
    const float* W1     = (const float*)d_in[11];
    const float* b1     = (const float*)d_in[12];
    const float* W2     = (const float*)d_in[13];
    const float* b2     = (const float*)d_in[14];
    const float* l1W    = (const float*)d_in[15];
    const float* l1b    = (const float*)d_in[16];
    const float* l2W    = (const float*)d_in[17];
    const float* l2b    = (const float*)d_in[18];
    float* out = (float*)d_out;

    int N = in_sizes[0] / 6;
    int E = in_sizes[1] / 2;
    int G = out_size;
    const int T = 256;
    int nb = (N + SCAN_BS - 1) / SCAN_BS;
    long long cw = (long long)N * 64 > E ? (long long)N * 64 : E;
    long long fb = E > N ? E : N;

    // build dst-CSR + dinv (xw1 and bounds ride along)
    k_zero_cnt<<<(N + T - 1) / T, T>>>(N);
    k_count_xw1<<<(int)((cw + T - 1) / T), T>>>(ei, x, W1, E, N);
    k_scan1<<<nb, SCAN_BS>>>(N);
    k_scan3<<<nb, SCAN_BS>>>(N, E);
    k_fill_bounds<<<(int)((fb + T - 1) / T), T>>>(ei, batch, E, N, G);

    // layer 1
    k_gather<<<(N * 8 + T - 1) / T, T>>>(N);

    // layer 2
    k_xw2<<<((N + 3) / 4 * 32 + T - 1) / T, T>>>(b1, W2, N);
    k_gather<<<(N * 8 + T - 1) / T, T>>>(N);

    // readout
    k_final<<<(G + 7) / 8, 256>>>(b2, lig, addv, bas, ary, e_l, e_a, e_b, e_r,
                                  l1W, l1b, l2W, l2b, out, G);
}

// round 15
// speedup vs baseline: 1.4117x; 1.1292x over previous
#include <cuda_runtime.h>
#include <cuda_fp16.h>

#define NMAX 100000
#define EMAX 1600000
#define GMAX 2048
#define SCAN_BS 512
#define NBLK_MAX ((NMAX + SCAN_BS - 1) / SCAN_BS)

// persistent scratch (no allocs allowed)
__device__ __align__(16) __half g_xwh[NMAX * 64];  // fp16 feature buffer (holds u = dinv*feat)
__device__ float g_h[NMAX * 64];      // fp32 aggregation output
__device__ float g_dinv[NMAX];        // rsqrt(degree)
__device__ int   g_cnt[NMAX];         // in-degree counts
__device__ int   g_rowptr[NMAX + 1];  // CSR row pointers (by dst)
__device__ int   g_cur[NMAX];         // fill cursors
__device__ int   g_csrc[EMAX];        // CSR src ids (weights factored out!)
__device__ int   g_bsum[NBLK_MAX];    // scan block sums
__device__ int   g_start[GMAX + 1];   // graph row boundaries

__global__ void k_zero_cnt(int N) {
    int i = blockIdx.x * blockDim.x + threadIdx.x;
    if (i < N) g_cnt[i] = 0;
}

// fused: degree count (RED, no return — id < E) + xw1 = x@W1 -> half (id < N*64)
__global__ void k_count_xw1(const int* __restrict__ ei,
                            const float* __restrict__ x,
                            const float* __restrict__ W1, int E, int N) {
    __shared__ float sW[6 * 64];
    for (int t = threadIdx.x; t < 384; t += blockDim.x) sW[t] = W1[t];
    __syncthreads();
    int id = blockIdx.x * blockDim.x + threadIdx.x;
    if (id < E) atomicAdd(&g_cnt[ei[E + id]], 1);
    int row = id >> 6, col = id & 63;
    if (row < N) {
        const float* xr = x + row * 6;
        float s = 0.f;
#pragma unroll
        for (int k = 0; k < 6; k++) s += xr[k] * sW[k * 64 + col];
        g_xwh[id] = __float2half_rn(s);
    }
}

// per-block inclusive scan -> exclusive within block + block totals
__global__ void k_scan1(int N) {
    __shared__ int sh[SCAN_BS];
    int i = blockIdx.x * SCAN_BS + threadIdx.x;
    int v = (i < N) ? g_cnt[i] : 0;
    sh[threadIdx.x] = v;
    __syncthreads();
#pragma unroll
    for (int off = 1; off < SCAN_BS; off <<= 1) {
        int t = (threadIdx.x >= off) ? sh[threadIdx.x - off] : 0;
        __syncthreads();
        sh[threadIdx.x] += t;
        __syncthreads();
    }
    if (i < N) g_rowptr[i] = sh[threadIdx.x] - v;
    if (threadIdx.x == SCAN_BS - 1) g_bsum[blockIdx.x] = sh[threadIdx.x];
}

// block offset (redundant reduce) + rowptr finalize + cursor init + dinv
__global__ void k_scan3(int N, int E) {
    __shared__ int warp_part[SCAN_BS / 32];
    __shared__ int s_off;
    int part = 0;
    for (int j = threadIdx.x; j < blockIdx.x; j += SCAN_BS) part += g_bsum[j];
#pragma unroll
    for (int o = 16; o; o >>= 1) part += __shfl_down_sync(0xffffffffu, part, o);
    if ((threadIdx.x & 31) == 0) warp_part[threadIdx.x >> 5] = part;
    __syncthreads();
    if (threadIdx.x == 0) {
        int t = 0;
#pragma unroll
        for (int w = 0; w < SCAN_BS / 32; w++) t += warp_part[w];
        s_off = t;
    }
    __syncthreads();
    int i = blockIdx.x * SCAN_BS + threadIdx.x;
    if (i < N) {
        int rp = g_rowptr[i] + s_off;
        g_rowptr[i] = rp;
        g_cur[i] = rp;
        g_dinv[i] = rsqrtf((float)(g_cnt[i] + 1));
        if (i == 0) g_rowptr[N] = E;
    }
}

// fused: CSR fill (src only, NO dinv reads — id < E) + graph bounds (id < N)
//        + u1 prescale: g_xwh *= dinv[node]  (id < N*16, one uint2 = 4 halves each)
__global__ void k_fill_bounds(const int* __restrict__ ei,
                              const int* __restrict__ batch,
                              int E, int N, int G) {
    int id = blockIdx.x * blockDim.x + threadIdx.x;
    if (id < E) {
        int s = ei[id];
        int d = ei[E + id];
        int pos = atomicAdd(&g_cur[d], 1);
        g_csrc[pos] = s;
    }
    if (id < N * 16) {
        float di = g_dinv[id >> 4];
        uint2* p = (uint2*)g_xwh;
        uint2 v = p[id];
        __half2* h = (__half2*)&v;
#pragma unroll
        for (int j = 0; j < 2; j++) {
            float2 f = __half22float2(h[j]);
            h[j] = __floats2half2_rn(f.x * di, f.y * di);
        }
        p[id] = v;
    }
    if (id < N) {
        int b = batch[id];
        if (id == 0) {
            for (int g2 = 0; g2 <= b; g2++) g_start[g2] = 0;
        } else {
            int pb = batch[id - 1];
            for (int g2 = pb + 1; g2 <= b; g2++) g_start[g2] = id;
        }
        if (id == N - 1) {
            for (int g2 = b + 1; g2 <= G; g2++) g_start[g2] = N;
        }
    }
}

__device__ __forceinline__ void h8_add(float* acc, uint4 r) {
    __half2* h = (__half2*)&r;
#pragma unroll
    for (int i = 0; i < 4; i++) {
        float2 f = __half22float2(h[i]);
        acc[2 * i]     += f.x;
        acc[2 * i + 1] += f.y;
    }
}

// CSR gather: g_h[n,:] = dinv[n] * (u[n,:] + sum_e u[src_e,:])
// 8 threads/node, one uint4 (8 halves) each; 2-way unroll (R4 proven shape)
__global__ void k_gather(int N) {
    int id = blockIdx.x * blockDim.x + threadIdx.x;
    int n = id >> 3;
    if (n >= N) return;
    int c = id & 7;
    const uint4* __restrict__ xw4 = (const uint4*)g_xwh;  // row = 8 uint4
    float di = g_dinv[n];
    float A[8] = {0, 0, 0, 0, 0, 0, 0, 0};
    float B[8] = {0, 0, 0, 0, 0, 0, 0, 0};
    h8_add(A, xw4[n * 8 + c]);
    int k = g_rowptr[n], end = g_rowptr[n + 1];
    for (; k + 1 < end; k += 2) {
        int s0 = g_csrc[k];
        int s1 = g_csrc[k + 1];
        uint4 r0 = xw4[s0 * 8 + c];
        uint4 r1 = xw4[s1 * 8 + c];
        h8_add(A, r0);
        h8_add(B, r1);
    }
    if (k < end) {
        int s0 = g_csrc[k];
        h8_add(A, xw4[s0 * 8 + c]);
    }
    float4* out4 = (float4*)(g_h + n * 64 + c * 8);
    out4[0] = make_float4((A[0] + B[0]) * di, (A[1] + B[1]) * di,
                          (A[2] + B[2]) * di, (A[3] + B[3]) * di);
    out4[1] = make_float4((A[4] + B[4]) * di, (A[5] + B[5]) * di,
                          (A[6] + B[6]) * di, (A[7] + B[7]) * di);
}

// g_xwh = half(dinv[row] * (relu(g_h + b1) @ W2))  (4 rows/warp, register-blocked)
__global__ void k_xw2(const float* __restrict__ b1, const float* __restrict__ W, int N) {
    __shared__ float sW[64 * 64];
    for (int t = threadIdx.x; t < 4096; t += blockDim.x) sW[t] = W[t];
    __syncthreads();
    int wrp = (blockIdx.x * blockDim.x + threadIdx.x) >> 5;
    int lane = threadIdx.x & 31;
    int r0 = wrp * 4;
    if (r0 >= N) return;
    float bl = b1[lane], bh = b1[lane + 32];
    float alo[4], ahi[4];
#pragma unroll
    for (int r = 0; r < 4; r++) {
        int row = r0 + r;
        if (row < N) {
            alo[r] = fmaxf(g_h[row * 64 + lane] + bl, 0.f);
            ahi[r] = fmaxf(g_h[row * 64 + 32 + lane] + bh, 0.f);
        } else { alo[r] = 0.f; ahi[r] = 0.f; }
    }
    float s0[4] = {0.f, 0.f, 0.f, 0.f};
    float s1[4] = {0.f, 0.f, 0.f, 0.f};
#pragma unroll
    for (int k = 0; k < 32; k++) {
        float w0 = sW[k * 64 + lane];
        float w1 = sW[k * 64 + lane + 32];
#pragma unroll
        for (int r = 0; r < 4; r++) {
            float vv = __shfl_sync(0xffffffffu, alo[r], k);
            s0[r] += vv * w0;
            s1[r] += vv * w1;
        }
    }
#pragma unroll
    for (int k = 0; k < 32; k++) {
        float w0 = sW[(k + 32) * 64 + lane];
        float w1 = sW[(k + 32) * 64 + lane + 32];
#pragma unroll
        for (int r = 0; r < 4; r++) {
            float vv = __shfl_sync(0xffffffffu, ahi[r], k);
            s0[r] += vv * w0;
            s1[r] += vv * w1;
        }
    }
#pragma unroll
    for (int r = 0; r < 4; r++) {
        int row = r0 + r;
        if (row < N) {
            float dv = g_dinv[row];
            g_xwh[row * 64 + lane]      = __float2half_rn(s0[r] * dv);
            g_xwh[row * 64 + lane + 32] = __float2half_rn(s1[r] * dv);
        }
    }
}

// fused: relu(h2+b2) mean-pool + concat embeddings + lin1 + relu + lin2
__global__ void k_final(const float* __restrict__ b2,
                        const int* __restrict__ lig, const int* __restrict__ addv,
                        const int* __restrict__ bas, const int* __restrict__ ary,
                        const float* __restrict__ e_l, const float* __restrict__ e_a,
                        const float* __restrict__ e_b, const float* __restrict__ e_r,
                        const float* __restrict__ l1W, const float* __restrict__ l1b,
                        const float* __restrict__ l2W, const float* __restrict__ l2b,
                        float* __restrict__ out, int G) {
    __shared__ float cat[8][128];
    int lane = threadIdx.x & 31;
    int w = threadIdx.x >> 5;
    int g = blockIdx.x * 8 + w;
    if (g >= G) return;
    int s = g_start[g], e = g_start[g + 1];
    float bias0 = b2[lane], bias1 = b2[lane + 32];
    float a0 = 0.f, a1 = 0.f;
    for (int r = s; r < e; r++) {
        a0 += fmaxf(g_h[r * 64 + lane] + bias0, 0.f);
        a1 += fmaxf(g_h[r * 64 + 32 + lane] + bias1, 0.f);
    }
    float inv = 1.0f / fmaxf((float)(e - s), 1.0f);
    cat[w][lane] = a0 * inv;
    cat[w][lane + 32] = a1 * inv;
    if (lane < 16) {
        cat[w][64 + lane]  = e_l[lig[g] * 16 + lane];
        cat[w][80 + lane]  = e_a[addv[g] * 16 + lane];
        cat[w][96 + lane]  = e_b[bas[g] * 16 + lane];
        cat[w][112 + lane] = e_r[ary[g] * 16 + lane];
    }
    __syncwarp();
    float h0 = l1b[lane], h1 = l1b[lane + 32];
#pragma unroll 8
    for (int k = 0; k < 128; k++) {
        float v = cat[w][k];
        h0 += v * l1W[k * 64 + lane];
        h1 += v * l1W[k * 64 + lane + 32];
    }
    h0 = fmaxf(h0, 0.f);
    h1 = fmaxf(h1, 0.f);
    float p = h0 * l2W[lane] + h1 * l2W[lane + 32];
#pragma unroll
    for (int off = 16; off > 0; off >>= 1) p += __shfl_down_sync(0xffffffffu, p, off);
    if (lane == 0) out[g] = p + l2b[0];
}

extern "C" void kernel_launch(void* const* d_in, const int* in_sizes, int n_in,
                              void* d_out, int out_size) {
    const float* x      = (const float*)d_in[0];
    const int*   ei     = (const int*)d_in[1];
    const int*   batch  = (const int*)d_in[2];
    const int*   lig    = (const int*)d_in[3];
    const int*   addv   = (const int*)d_in[4];
    const int*   bas    = (const int*)d_in[5];
    const int*   ary    = (const int*)d_in[6];
    const float* e_l    = (const float*)d_in[7];
    const float* e_a    = (const float*)d_in[8];
    const float* e_b    = (const float*)d_in[9];
    const float* e_r    = (const float*)d_in[10];
    const float* W1     = (const float*)d_in[11];
    const float* b1     = (const float*)d_in[12];
    const float* W2     = (const float*)d_in[13];
    const float* b2     = (const float*)d_in[14];
    const float* l1W    = (const float*)d_in[15];
    const float* l1b    = (const float*)d_in[16];
    const float* l2W    = (const float*)d_in[17];
    const float* l2b    = (const float*)d_in[18];
    float* out = (float*)d_out;

    int N = in_sizes[0] / 6;
    int E = in_sizes[1] / 2;
    int G = out_size;
    const int T = 256;
    int nb = (N + SCAN_BS - 1) / SCAN_BS;
    long long cw = (long long)N * 64 > E ? (long long)N * 64 : E;
    long long fb = E > (long long)N * 16 ? E : (long long)N * 16;

    // build dst-CSR + dinv (xw1 and bounds ride along)
    k_zero_cnt<<<(N + T - 1) / T, T>>>(N);
    k_count_xw1<<<(int)((cw + T - 1) / T), T>>>(ei, x, W1, E, N);
    k_scan1<<<nb, SCAN_BS>>>(N);
    k_scan3<<<nb, SCAN_BS>>>(N, E);
    k_fill_bounds<<<(int)((fb + T - 1) / T), T>>>(ei, batch, E, N, G);

    // layer 1
    k_gather<<<(N * 8 + T - 1) / T, T>>>(N);

    // layer 2
    k_xw2<<<((N + 3) / 4 * 32 + T - 1) / T, T>>>(b1, W2, N);
    k_gather<<<(N * 8 + T - 1) / T, T>>>(N);

    // readout
    k_final<<<(G + 7) / 8, 256>>>(b2, lig, addv, bas, ary, e_l, e_a, e_b, e_r,
                                  l1W, l1b, l2W, l2b, out, G);
}

// round 16
// speedup vs baseline: 1.4473x; 1.0252x over previous
#include <cuda_runtime.h>
#include <cuda_fp16.h>
#include <mma.h>

#define NMAX 100000
#define EMAX 1600000
#define GMAX 2048
#define SCAN_BS 512
#define NBLK_MAX ((NMAX + SCAN_BS - 1) / SCAN_BS)

// persistent scratch (no allocs allowed)
__device__ __align__(16) __half g_xwh[NMAX * 64];  // fp16 feature buffer (holds u = dinv*feat)
__device__ float g_h[NMAX * 64];      // fp32 aggregation output
__device__ float g_dinv[NMAX];        // rsqrt(degree)
__device__ int   g_cnt[NMAX];         // in-degree counts
__device__ int   g_rowptr[NMAX + 1];  // CSR row pointers (by dst)
__device__ int   g_cur[NMAX];         // fill cursors
__device__ int   g_csrc[EMAX];        // CSR src ids (weights factored out)
__device__ int   g_bsum[NBLK_MAX];    // scan block sums
__device__ int   g_start[GMAX + 1];   // graph row boundaries
__device__ __align__(16) __half g_W2h[64 * 64];  // W2 in fp16 (for wmma)

__global__ void k_zero_cnt(int N) {
    int i = blockIdx.x * blockDim.x + threadIdx.x;
    if (i < N) g_cnt[i] = 0;
}

// bare degree count: REDG fire-and-forget
__global__ void k_count(const int* __restrict__ ei, int E) {
    int e = blockIdx.x * blockDim.x + threadIdx.x;
    if (e < E) atomicAdd(&g_cnt[ei[E + e]], 1);
}

// per-block inclusive scan -> exclusive within block + block totals
// block 0 also converts W2 fp32 -> fp16 for the wmma xw2 kernel
__global__ void k_scan1(const float* __restrict__ W2, int N) {
    __shared__ int sh[SCAN_BS];
    if (blockIdx.x == 0) {
        for (int t = threadIdx.x; t < 4096; t += SCAN_BS)
            g_W2h[t] = __float2half_rn(W2[t]);
    }
    int i = blockIdx.x * SCAN_BS + threadIdx.x;
    int v = (i < N) ? g_cnt[i] : 0;
    sh[threadIdx.x] = v;
    __syncthreads();
#pragma unroll
    for (int off = 1; off < SCAN_BS; off <<= 1) {
        int t = (threadIdx.x >= off) ? sh[threadIdx.x - off] : 0;
        __syncthreads();
        sh[threadIdx.x] += t;
        __syncthreads();
    }
    if (i < N) g_rowptr[i] = sh[threadIdx.x] - v;
    if (threadIdx.x == SCAN_BS - 1) g_bsum[blockIdx.x] = sh[threadIdx.x];
}

// block offset (redundant reduce) + rowptr finalize + cursor init + dinv
__global__ void k_scan3(int N, int E) {
    __shared__ int warp_part[SCAN_BS / 32];
    __shared__ int s_off;
    int part = 0;
    for (int j = threadIdx.x; j < blockIdx.x; j += SCAN_BS) part += g_bsum[j];
#pragma unroll
    for (int o = 16; o; o >>= 1) part += __shfl_down_sync(0xffffffffu, part, o);
    if ((threadIdx.x & 31) == 0) warp_part[threadIdx.x >> 5] = part;
    __syncthreads();
    if (threadIdx.x == 0) {
        int t = 0;
#pragma unroll
        for (int w = 0; w < SCAN_BS / 32; w++) t += warp_part[w];
        s_off = t;
    }
    __syncthreads();
    int i = blockIdx.x * SCAN_BS + threadIdx.x;
    if (i < N) {
        int rp = g_rowptr[i] + s_off;
        g_rowptr[i] = rp;
        g_cur[i] = rp;
        g_dinv[i] = rsqrtf((float)(g_cnt[i] + 1));
        if (i == 0) g_rowptr[N] = E;
    }
}

// fused: CSR fill (src only — id < E) + u1 = half(dinv*(x@W1)) (id < N*64)
//        + graph bounds (id < N). xw1's FFMA warps hide the fill ATOMG latency.
__global__ void k_fill_xw1_bounds(const int* __restrict__ ei,
                                  const int* __restrict__ batch,
                                  const float* __restrict__ x,
                                  const float* __restrict__ W1,
                                  int E, int N, int G) {
    __shared__ float sW[6 * 64];
    for (int t = threadIdx.x; t < 384; t += blockDim.x) sW[t] = W1[t];
    __syncthreads();
    int id = blockIdx.x * blockDim.x + threadIdx.x;
    if (id < E) {
        int s = ei[id];
        int d = ei[E + id];
        int pos = atomicAdd(&g_cur[d], 1);
        g_csrc[pos] = s;
    }
    int row = id >> 6, col = id & 63;
    if (row < N) {
        const float* xr = x + row * 6;
        float s = 0.f;
#pragma unroll
        for (int k = 0; k < 6; k++) s += xr[k] * sW[k * 64 + col];
        g_xwh[id] = __float2half_rn(s * g_dinv[row]);
    }
    if (id < N) {
        int b = batch[id];
        if (id == 0) {
            for (int g2 = 0; g2 <= b; g2++) g_start[g2] = 0;
        } else {
            int pb = batch[id - 1];
            for (int g2 = pb + 1; g2 <= b; g2++) g_start[g2] = id;
        }
        if (id == N - 1) {
            for (int g2 = b + 1; g2 <= G; g2++) g_start[g2] = N;
        }
    }
}

__device__ __forceinline__ void h8_add(float* acc, uint4 r) {
    __half2* h = (__half2*)&r;
#pragma unroll
    for (int i = 0; i < 4; i++) {
        float2 f = __half22float2(h[i]);
        acc[2 * i]     += f.x;
        acc[2 * i + 1] += f.y;
    }
}

// CSR gather: g_h[n,:] = dinv[n] * (u[n,:] + sum_e u[src_e,:])
// 8 threads/node, one uint4 (8 halves) each; 2-way unroll (proven shape)
__global__ void k_gather(int N) {
    int id = blockIdx.x * blockDim.x + threadIdx.x;
    int n = id >> 3;
    if (n >= N) return;
    int c = id & 7;
    const uint4* __restrict__ xw4 = (const uint4*)g_xwh;  // row = 8 uint4
    float di = g_dinv[n];
    float A[8] = {0, 0, 0, 0, 0, 0, 0, 0};
    float B[8] = {0, 0, 0, 0, 0, 0, 0, 0};
    h8_add(A, xw4[n * 8 + c]);
    int k = g_rowptr[n], end = g_rowptr[n + 1];
    for (; k + 1 < end; k += 2) {
        int s0 = g_csrc[k];
        int s1 = g_csrc[k + 1];
        uint4 r0 = xw4[s0 * 8 + c];
        uint4 r1 = xw4[s1 * 8 + c];
        h8_add(A, r0);
        h8_add(B, r1);
    }
    if (k < end) {
        int s0 = g_csrc[k];
        h8_add(A, xw4[s0 * 8 + c]);
    }
    float4* out4 = (float4*)(g_h + n * 64 + c * 8);
    out4[0] = make_float4((A[0] + B[0]) * di, (A[1] + B[1]) * di,
                          (A[2] + B[2]) * di, (A[3] + B[3]) * di);
    out4[1] = make_float4((A[4] + B[4]) * di, (A[5] + B[5]) * di,
                          (A[6] + B[6]) * di, (A[7] + B[7]) * di);
}

// wmma xw2: g_xwh = half(dinv[row] * (relu(g_h + b1) @ W2))
// block = 256 thr (8 warps), 32 rows; warp w: rowtile w>>2, coltile w&3
__global__ void __launch_bounds__(256) k_xw2_wmma(const float* __restrict__ b1, int N) {
    using namespace nvcuda::wmma;
    __shared__ __half sA[32 * 64];
    __shared__ __half sW[64 * 64];
    __shared__ float  sC[32 * 64];
    int tid = threadIdx.x;
    int r0 = blockIdx.x * 32;
    // stage W2 (fp16, pre-converted)
    for (int t = tid; t < 2048; t += 256)
        ((uint2*)sW)[t] = ((const uint2*)g_W2h)[t];
    // stage A = half(relu(g_h + b1)), 8 elems/thread
    {
        int base = tid * 8;            // 0..2047
        int row = base >> 6;
        int col = base & 63;
        int grow = r0 + row;
        float4 v0, v1;
        if (grow < N) {
            const float4* p = (const float4*)(g_h + grow * 64 + col);
            v0 = p[0]; v1 = p[1];
        } else {
            v0 = make_float4(0, 0, 0, 0); v1 = make_float4(0, 0, 0, 0);
        }
        const float* bb = b1 + col;
        __half2 h[4];
        h[0] = __floats2half2_rn(fmaxf(v0.x + bb[0], 0.f), fmaxf(v0.y + bb[1], 0.f));
        h[1] = __floats2half2_rn(fmaxf(v0.z + bb[2], 0.f), fmaxf(v0.w + bb[3], 0.f));
        h[2] = __floats2half2_rn(fmaxf(v1.x + bb[4], 0.f), fmaxf(v1.y + bb[5], 0.f));
        h[3] = __floats2half2_rn(fmaxf(v1.z + bb[6], 0.f), fmaxf(v1.w + bb[7], 0.f));
        *((uint4*)(sA + base)) = *(uint4*)h;
    }
    __syncthreads();
    {
        int w = tid >> 5;
        int rt = w >> 2;        // 0..1
        int ct = w & 3;         // 0..3
        fragment<accumulator, 16, 16, 16, float> c;
        fill_fragment(c, 0.0f);
#pragma unroll
        for (int k = 0; k < 4; k++) {
            fragment<matrix_a, 16, 16, 16, __half, row_major> a;
            fragment<matrix_b, 16, 16, 16, __half, row_major> b;
            load_matrix_sync(a, sA + rt * 16 * 64 + k * 16, 64);
            load_matrix_sync(b, sW + k * 16 * 64 + ct * 16, 64);
            mma_sync(c, a, b, c);
        }
        store_matrix_sync(sC + rt * 16 * 64 + ct * 16, c, 64, mem_row_major);
    }
    __syncthreads();
    // epilogue: scale by dinv[row], pack fp16, write
    {
        int base = tid * 8;
        int row = base >> 6;
        int grow = r0 + row;
        if (grow < N) {
            float dv = g_dinv[grow];
            const float* cp = sC + base;
            __half2 h[4];
#pragma unroll
            for (int j = 0; j < 4; j++)
                h[j] = __floats2half2_rn(cp[2 * j] * dv, cp[2 * j + 1] * dv);
            ((uint4*)g_xwh)[(grow * 64 + (base & 63)) >> 3] = *(uint4*)h;
        }
    }
}

// fused: relu(h2+b2) mean-pool + concat embeddings + lin1 + relu + lin2
__global__ void k_final(const float* __restrict__ b2,
                        const int* __restrict__ lig, const int* __restrict__ addv,
                        const int* __restrict__ bas, const int* __restrict__ ary,
                        const float* __restrict__ e_l, const float* __restrict__ e_a,
                        const float* __restrict__ e_b, const float* __restrict__ e_r,
                        const float* __restrict__ l1W, const float* __restrict__ l1b,
                        const float* __restrict__ l2W, const float* __restrict__ l2b,
                        float* __restrict__ out, int G) {
    __shared__ float cat[8][128];
    int lane = threadIdx.x & 31;
    int w = threadIdx.x >> 5;
    int g = blockIdx.x * 8 + w;
    if (g >= G) return;
    int s = g_start[g], e = g_start[g + 1];
    float bias0 = b2[lane], bias1 = b2[lane + 32];
    float a0 = 0.f, a1 = 0.f;
    for (int r = s; r < e; r++) {
        a0 += fmaxf(g_h[r * 64 + lane] + bias0, 0.f);
        a1 += fmaxf(g_h[r * 64 + 32 + lane] + bias1, 0.f);
    }
    float inv = 1.0f / fmaxf((float)(e - s), 1.0f);
    cat[w][lane] = a0 * inv;
    cat[w][lane + 32] = a1 * inv;
    if (lane < 16) {
        cat[w][64 + lane]  = e_l[lig[g] * 16 + lane];
        cat[w][80 + lane]  = e_a[addv[g] * 16 + lane];
        cat[w][96 + lane]  = e_b[bas[g] * 16 + lane];
        cat[w][112 + lane] = e_r[ary[g] * 16 + lane];
    }
    __syncwarp();
    float h0 = l1b[lane], h1 = l1b[lane + 32];
#pragma unroll 8
    for (int k = 0; k < 128; k++) {
        float v = cat[w][k];
        h0 += v * l1W[k * 64 + lane];
        h1 += v * l1W[k * 64 + lane + 32];
    }
    h0 = fmaxf(h0, 0.f);
    h1 = fmaxf(h1, 0.f);
    float p = h0 * l2W[lane] + h1 * l2W[lane + 32];
#pragma unroll
    for (int off = 16; off > 0; off >>= 1) p += __shfl_down_sync(0xffffffffu, p, off);
    if (lane == 0) out[g] = p + l2b[0];
}

extern "C" void kernel_launch(void* const* d_in, const int* in_sizes, int n_in,
                              void* d_out, int out_size) {
    const float* x      = (const float*)d_in[0];
    const int*   ei     = (const int*)d_in[1];
    const int*   batch  = (const int*)d_in[2];
    const int*   lig    = (const int*)d_in[3];
    const int*   addv   = (const int*)d_in[4];
    const int*   bas    = (const int*)d_in[5];
    const int*   ary    = (const int*)d_in[6];
    const float* e_l    = (const float*)d_in[7];
    const float* e_a    = (const float*)d_in[8];
    const float* e_b    = (const float*)d_in[9];
    const float* e_r    = (const float*)d_in[10];
    const float* W1     = (const float*)d_in[11];
    const float* b1     = (const float*)d_in[12];
    const float* W2     = (const float*)d_in[13];
    const float* b2     = (const float*)d_in[14];
    const float* l1W    = (const float*)d_in[15];
    const float* l1b    = (const float*)d_in[16];
    const float* l2W    = (const float*)d_in[17];
    const float* l2b    = (const float*)d_in[18];
    float* out = (float*)d_out;

    int N = in_sizes[0] / 6;
    int E = in_sizes[1] / 2;
    int G = out_size;
    const int T = 256;
    int nb = (N + SCAN_BS - 1) / SCAN_BS;
    long long fw = (long long)N * 64 > E ? (long long)N * 64 : E;

    // build dst-CSR + dinv
    k_zero_cnt<<<(N + T - 1) / T, T>>>(N);
    k_count<<<(E + T - 1) / T, T>>>(ei, E);
    k_scan1<<<nb, SCAN_BS>>>(W2, N);
    k_scan3<<<nb, SCAN_BS>>>(N, E);
    k_fill_xw1_bounds<<<(int)((fw + T - 1) / T), T>>>(ei, batch, x, W1, E, N, G);

    // layer 1
    k_gather<<<(N * 8 + T - 1) / T, T>>>(N);

    // layer 2 (tensor-core xw2)
    k_xw2_wmma<<<(N + 31) / 32, 256>>>(b1, N);
    k_gather<<<(N * 8 + T - 1) / T, T>>>(N);

    // readout
    k_final<<<(G + 7) / 8, 256>>>(b2, lig, addv, bas, ary, e_l, e_a, e_b, e_r,
                                  l1W, l1b, l2W, l2b, out, G);
}